// round 9
// baseline (speedup 1.0000x reference)
#include <cuda_runtime.h>
#include <cuda_fp16.h>
#include <cstdint>

// ---------------- problem constants ----------------
#define BATCH 32
#define CH    256
#define HH    56
#define WW    56
#define HPAD  58
#define WPAD  64
#define HO    28
#define WO    28
#define NPIX  (BATCH*HH*WW)      // 100352
#define PPB   (HPAD*WPAD)        // padded pixels per image = 3712

// conv tiling: CTA M=128 pixels x N=128 ch, 4 warps (warp tile 64x64),
// K-chunk 32 per stage
#define NT        128
#define AROWS     130            // 128 pixels + 2 shift halo
#define RSTRB     80             // smem row stride bytes (40 halves)
#define RSTRH     40             // stride in halves
#define AOFF      0
#define BOFF      (AROWS*RSTRB)                        // 10400
#define STAGE     ((BOFF + 384*RSTRB + 127) & ~127)    // 41216
#define NSTAGE    2
#define DSMEM     (NSTAGE*STAGE)                       // 82432 -> 2 CTAs/SM
#define NTHR      128

// ---------------- static scratch (zero-initialized) ----------------
__device__ __align__(128) __half g_xpad[(size_t)BATCH*PPB*CH + 4096]; // [n][hp][wp][c]
__device__ __align__(128) __half g_wpack[9*256*256];                  // [rs][o][c]
__device__ __align__(128) __half g_ybuf[(size_t)NPIX*CH];             // NHWC conv out
__device__ float g_sum[256], g_sumsq[256], g_scale[256], g_shift[256];

// ---------------- helpers ----------------
__device__ __forceinline__ uint32_t su32(const void* p) {
    uint32_t a;
    asm("{.reg .u64 t; cvta.to.shared.u64 t, %1; cvt.u32.u64 %0, t;}" : "=r"(a) : "l"(p));
    return a;
}
__device__ __forceinline__ void cp16(uint32_t dst, const void* src) {
    asm volatile("cp.async.cg.shared.global [%0], [%1], 16;" :: "r"(dst), "l"(src));
}

// ---------------------------------------------------------------------------
// Kernel 1: pack weights -> sign fp16 [rs][o][c]; block 0 zeroes stats
// ---------------------------------------------------------------------------
__global__ __launch_bounds__(256) void pack_w_kernel(const float* __restrict__ W)
{
    int idx = blockIdx.x * 256 + threadIdx.x;     // 0 .. 589823
    int c  = idx & 255;
    int o  = (idx >> 8) & 255;
    int rs = idx >> 16;
    int r  = rs / 3;
    int s  = rs - 3 * r;
    float v = W[(((size_t)o * 256 + c) * 3 + r) * 3 + s];
    float sv = (v > 0.f) ? 1.f : ((v < 0.f) ? -1.f : 0.f);
    g_wpack[idx] = __float2half(sv);
    if (blockIdx.x == 0) {
        g_sum[threadIdx.x]   = 0.f;
        g_sumsq[threadIdx.x] = 0.f;
    }
}

// ---------------------------------------------------------------------------
// Kernel 2: transpose-pack x NCHW fp32 -> [n][hp][wp][c] fp16
// ---------------------------------------------------------------------------
__global__ __launch_bounds__(256) void pack_x_kernel(const float* __restrict__ x)
{
    __shared__ __half sm[256][58];
    const int h = blockIdx.x, n = blockIdx.y;
    const int wi = threadIdx.x & 63, cb = threadIdx.x >> 6;   // cb 0..3
    if (wi < 56) {
        const float* src = x + (((size_t)n * 256 + cb) * 56 + h) * 56 + wi;
        #pragma unroll 8
        for (int c8 = 0; c8 < 64; c8++) {
            sm[c8 * 4 + cb][wi] = __float2half(src[(size_t)c8 * 4 * 56 * 56]);
        }
    }
    __syncthreads();
    for (int chunk = threadIdx.x; chunk < 56 * 32; chunk += 256) {
        int w = chunk >> 5, cq = chunk & 31;
        __half tmp[8];
        #pragma unroll
        for (int j = 0; j < 8; j++) tmp[j] = sm[cq * 8 + j][w];
        *(uint4*)(g_xpad + (((size_t)(n * HPAD + h + 1)) * WPAD + (w + 1)) * CH + cq * 8)
            = *(uint4*)tmp;
    }
}

// dummy: positions conv as launch #4 so ncu's fixed sample window hits it
__global__ void dummy_kernel() {}

// ---------------------------------------------------------------------------
// Kernel 3: conv via mma.sync, 64x64 warp tiles (128B LDS per MMA),
// 2-deep cp.async ring, 2 CTAs/SM, fused BN stats.
// grid (2 ch-tiles, 28 h-tiles, 32 n) = 1792 CTAs, 128 thr (4 warps: 2m x 2n).
// 24 smem stages = 3 h-taps x 8 blocks of 32 in-ch.
// ---------------------------------------------------------------------------
__global__ __launch_bounds__(NTHR, 2) void conv_kernel()
{
    extern __shared__ __align__(128) char dsm[];
    __shared__ float sm_s1[128];
    __shared__ float sm_s2[128];

    const int n0  = blockIdx.x * NT;
    const int h0  = blockIdx.y * 2;
    const int nb  = blockIdx.z;
    const int tid = threadIdx.x;
    const int wid = tid >> 5, lane = tid & 31;
    const int g = lane >> 2, t = lane & 3;
    const int warp_m = wid & 1;               // 64 pixels (one h-row) each
    const int warp_n = wid >> 1;              // 64 channels each

    float acc[4][8][4];
    #pragma unroll
    for (int a = 0; a < 4; a++)
        #pragma unroll
        for (int b = 0; b < 8; b++)
            #pragma unroll
            for (int c = 0; c < 4; c++) acc[a][b][c] = 0.f;

    sm_s1[tid] = 0.f; sm_s2[tid] = 0.f;

    const __half* xp = g_xpad + (size_t)nb * PPB * CH;

    auto load_stage = [&](int st) {
        char* sb = dsm + (st & 1) * STAGE;
        const int r = st >> 3, kb = st & 7;        // kb: 32-ch block
        const int pix0 = (h0 + r) * WPAD;
        // A: 130 consecutive padded pixels x 32 ch (4 x 16B chunks per row)
        #pragma unroll 1
        for (int i = tid; i < AROWS * 4; i += NTHR) {
            int row = i >> 2, q = i & 3;
            cp16(su32(sb + AOFF + row * RSTRB + q * 16),
                 xp + (size_t)(pix0 + row) * CH + kb * 32 + q * 8);
        }
        // B: 3 taps x 128 out-ch x 32 in-ch
        const __half* wp = g_wpack + (size_t)(r * 3) * 65536 + (size_t)n0 * 256 + kb * 32;
        #pragma unroll 1
        for (int i = tid; i < 1536; i += NTHR) {
            int tap = i >> 9, rem = i & 511, nn = rem >> 2, q = rem & 3;
            cp16(su32(sb + BOFF + (tap * 128 + nn) * RSTRB + q * 16),
                 wp + (size_t)tap * 65536 + (size_t)nn * 256 + q * 8);
        }
        asm volatile("cp.async.commit_group;" ::: "memory");
    };

    auto compute = [&](int st) {
        const char* sb = dsm + (st & 1) * STAGE;
        const __half* sA = (const __half*)(sb + AOFF);
        const __half* sB = (const __half*)(sb + BOFF);
        #pragma unroll
        for (int s = 0; s < 3; s++) {
            #pragma unroll
            for (int kk = 0; kk < 2; kk++) {
                const int c0 = kk * 16 + 2 * t;
                uint32_t af[4][4];
                #pragma unroll
                for (int mt = 0; mt < 4; mt++) {
                    int row = warp_m * 64 + mt * 16 + g + s;
                    af[mt][0] = *(const uint32_t*)(sA + row * RSTRH + c0);
                    af[mt][1] = *(const uint32_t*)(sA + (row + 8) * RSTRH + c0);
                    af[mt][2] = *(const uint32_t*)(sA + row * RSTRH + c0 + 8);
                    af[mt][3] = *(const uint32_t*)(sA + (row + 8) * RSTRH + c0 + 8);
                }
                uint32_t bf[8][2];
                #pragma unroll
                for (int nt = 0; nt < 8; nt++) {
                    int nn = s * 128 + warp_n * 64 + nt * 8 + g;
                    bf[nt][0] = *(const uint32_t*)(sB + nn * RSTRH + c0);
                    bf[nt][1] = *(const uint32_t*)(sB + nn * RSTRH + c0 + 8);
                }
                #pragma unroll
                for (int mt = 0; mt < 4; mt++) {
                    #pragma unroll
                    for (int nt = 0; nt < 8; nt++) {
                        float* cacc = acc[mt][nt];
                        asm volatile(
                          "mma.sync.aligned.m16n8k16.row.col.f32.f16.f16.f32 "
                          "{%0,%1,%2,%3}, {%4,%5,%6,%7}, {%8,%9}, {%0,%1,%2,%3};\n"
                          : "+f"(cacc[0]), "+f"(cacc[1]), "+f"(cacc[2]), "+f"(cacc[3])
                          : "r"(af[mt][0]), "r"(af[mt][1]), "r"(af[mt][2]), "r"(af[mt][3]),
                            "r"(bf[nt][0]), "r"(bf[nt][1]));
                    }
                }
            }
        }
    };

    load_stage(0);
    load_stage(1);
    #pragma unroll 1
    for (int st = 0; st < 24; st++) {
        if (st < 23)
            asm volatile("cp.async.wait_group 1;" ::: "memory");
        else
            asm volatile("cp.async.wait_group 0;" ::: "memory");
        __syncthreads();                 // stage st visible to all warps
        compute(st);
        if (st + 2 < 24) {
            __syncthreads();             // all warps done reading slot st
            load_stage(st + 2);
        }
    }

    // ---- epilogue: acc -> fp16 NHWC + fused BN stats ----
    const int h = h0 + warp_m;
    float s1[8][2], s2[8][2];
    #pragma unroll
    for (int nt = 0; nt < 8; nt++) { s1[nt][0]=s1[nt][1]=s2[nt][0]=s2[nt][1]=0.f; }

    #pragma unroll
    for (int nt = 0; nt < 8; nt++) {
        const int ch0 = n0 + warp_n * 64 + nt * 8 + 2 * t;
        #pragma unroll
        for (int mt = 0; mt < 4; mt++) {
            int w0 = mt * 16 + g;            // < 56 always
            float f0 = acc[mt][nt][0], f1 = acc[mt][nt][1];
            __half2 hv = __floats2half2_rn(f0, f1);
            *(__half2*)(g_ybuf + (((size_t)(nb * HH + h) * WW + w0) * CH) + ch0) = hv;
            s1[nt][0] += f0;  s2[nt][0] += f0 * f0;
            s1[nt][1] += f1;  s2[nt][1] += f1 * f1;
            if (mt < 3) {                    // w0+8 valid only for mt<3
                int w1 = w0 + 8;
                float f2 = acc[mt][nt][2], f3 = acc[mt][nt][3];
                __half2 hv2 = __floats2half2_rn(f2, f3);
                *(__half2*)(g_ybuf + (((size_t)(nb * HH + h) * WW + w1) * CH) + ch0) = hv2;
                s1[nt][0] += f2;  s2[nt][0] += f2 * f2;
                s1[nt][1] += f3;  s2[nt][1] += f3 * f3;
            }
        }
    }
    #pragma unroll
    for (int nt = 0; nt < 8; nt++) {
        #pragma unroll
        for (int p = 0; p < 2; p++) {
            #pragma unroll
            for (int m = 4; m < 32; m <<= 1) {
                s1[nt][p] += __shfl_xor_sync(0xffffffffu, s1[nt][p], m);
                s2[nt][p] += __shfl_xor_sync(0xffffffffu, s2[nt][p], m);
            }
        }
    }
    __syncthreads();
    if (g == 0) {
        #pragma unroll
        for (int nt = 0; nt < 8; nt++) {
            #pragma unroll
            for (int p = 0; p < 2; p++) {
                int chl = warp_n * 64 + nt * 8 + 2 * t + p;
                atomicAdd(&sm_s1[chl], s1[nt][p]);
                atomicAdd(&sm_s2[chl], s2[nt][p]);
            }
        }
    }
    __syncthreads();
    atomicAdd(&g_sum[n0 + tid],   sm_s1[tid]);
    atomicAdd(&g_sumsq[n0 + tid], sm_s2[tid]);
}

// ---------------------------------------------------------------------------
// Kernel 4: finalize BN stats -> scale/shift
// ---------------------------------------------------------------------------
__global__ void stats_kernel(const float* __restrict__ gamma,
                             const float* __restrict__ beta)
{
    int c = threadIdx.x;
    const float inv = 1.f / (float)NPIX;
    float m   = g_sum[c] * inv;
    float var = g_sumsq[c] * inv - m * m;
    float sc  = gamma[c] * rsqrtf(var + 1e-5f);
    g_scale[c] = sc;
    g_shift[c] = beta[c] - m * sc;
}

// ---------------------------------------------------------------------------
// Kernel 5: normalize + ReLU + 2x2 maxpool, NHWC fp16 -> NCHW fp32
// ---------------------------------------------------------------------------
__global__ __launch_bounds__(256) void pool_kernel(float* __restrict__ out)
{
    __shared__ float sm[256 * WO];
    const int ho = blockIdx.x;
    const int n  = blockIdx.y;
    const int c  = threadIdx.x;
    const float sc = g_scale[c];
    const float sh = g_shift[c];
    const __half* b0 = g_ybuf + ((size_t)(n * HH + 2 * ho) * WW) * CH + c;
    const __half* b1 = b0 + (size_t)WW * CH;
    #pragma unroll 4
    for (int wo = 0; wo < WO; wo++) {
        float a0 = __half2float(b0[(size_t)(2 * wo)     * CH]);
        float a1 = __half2float(b0[(size_t)(2 * wo + 1) * CH]);
        float a2 = __half2float(b1[(size_t)(2 * wo)     * CH]);
        float a3 = __half2float(b1[(size_t)(2 * wo + 1) * CH]);
        float r0 = fmaxf(a0 * sc + sh, 0.f);
        float r1 = fmaxf(a1 * sc + sh, 0.f);
        float r2 = fmaxf(a2 * sc + sh, 0.f);
        float r3 = fmaxf(a3 * sc + sh, 0.f);
        sm[c * WO + wo] = fmaxf(fmaxf(r0, r1), fmaxf(r2, r3));
    }
    __syncthreads();
    for (int i = threadIdx.x; i < 256 * WO; i += 256) {
        int cc = i / WO, wo = i % WO;
        out[(((size_t)n * CH + cc) * HO + ho) * WO + wo] = sm[i];
    }
}

// ---------------------------------------------------------------------------
extern "C" void kernel_launch(void* const* d_in, const int* in_sizes, int n_in,
                              void* d_out, int out_size)
{
    const float* x     = (const float*)d_in[0];
    const float* W     = (const float*)d_in[1];
    const float* gamma = (const float*)d_in[2];
    const float* beta  = (const float*)d_in[3];
    float* out = (float*)d_out;

    pack_w_kernel<<<2304, 256>>>(W);
    pack_x_kernel<<<dim3(HH, BATCH), 256>>>(x);
    dummy_kernel<<<1, 32>>>();          // keep conv in ncu's sample slot (#4)

    cudaFuncSetAttribute(conv_kernel, cudaFuncAttributeMaxDynamicSharedMemorySize, DSMEM);
    conv_kernel<<<dim3(2, HH / 2, BATCH), NTHR, DSMEM>>>();

    stats_kernel<<<1, 256>>>(gamma, beta);
    pool_kernel<<<dim3(HO, BATCH), 256>>>(out);
}

// round 10
// speedup vs baseline: 1.0994x; 1.0994x over previous
#include <cuda_runtime.h>
#include <cuda_fp16.h>
#include <cstdint>

// ---------------- problem constants ----------------
#define BATCH 32
#define CH    256
#define HH    56
#define WW    56
#define HO    28
#define WO    28
#define NPIX  (BATCH*HH*WW)      // 100352 valid output pixels
#define PROW  58                 // padded row width
#define PIMG  (58*58)            // padded pixels per image = 3364
#define FVAL  (HH*PROW)          // flat range containing valid outputs = 3248
#define MT_PER_IMG 26            // ceil(3248/128)

// conv tiling: CTA M=128 flat pixels x N=128 ch, K-chunk 32 per stage
#define NT        128
#define AROWS     130            // 128 pixels + 2 shift halo
#define RSTRB     80             // smem row stride bytes (40 halves)
#define RSTRH     40
#define AOFF      0
#define BOFF      (AROWS*RSTRB)                        // 10400
#define STAGE     ((BOFF + 384*RSTRB + 127) & ~127)    // 41216
#define DSMEM     (2*STAGE)                            // 82432 -> 2 CTAs/SM

// ---------------- static scratch (zero-initialized) ----------------
__device__ __align__(128) __half g_xpad[(size_t)BATCH*PIMG*CH + 32768]; // [n][f][c]
__device__ __align__(128) __half g_wpack[9*256*256];                    // [rs][o][c]
__device__ __align__(128) __half g_ybuf[(size_t)NPIX*CH];               // NHWC conv out
__device__ float g_sum[256], g_sumsq[256];

// ---------------- helpers ----------------
__device__ __forceinline__ uint32_t su32(const void* p) {
    uint32_t a;
    asm("{.reg .u64 t; cvta.to.shared.u64 t, %1; cvt.u32.u64 %0, t;}" : "=r"(a) : "l"(p));
    return a;
}
__device__ __forceinline__ void cp16(uint32_t dst, const void* src) {
    asm volatile("cp.async.cg.shared.global [%0], [%1], 16;" :: "r"(dst), "l"(src));
}

// ---------------------------------------------------------------------------
// Kernel 1: pack weights -> sign fp16 [rs][o][c]; block 0 zeroes stats
// ---------------------------------------------------------------------------
__global__ __launch_bounds__(256) void pack_w_kernel(const float* __restrict__ W)
{
    int idx = blockIdx.x * 256 + threadIdx.x;     // 0 .. 589823
    int c  = idx & 255;
    int o  = (idx >> 8) & 255;
    int rs = idx >> 16;
    int r  = rs / 3;
    int s  = rs - 3 * r;
    float v = W[(((size_t)o * 256 + c) * 3 + r) * 3 + s];
    float sv = (v > 0.f) ? 1.f : ((v < 0.f) ? -1.f : 0.f);
    g_wpack[idx] = __float2half(sv);
    if (blockIdx.x == 0) {
        g_sum[threadIdx.x]   = 0.f;
        g_sumsq[threadIdx.x] = 0.f;
    }
}

// ---------------------------------------------------------------------------
// Kernel 2: transpose-pack x NCHW fp32 -> flat padded [n][(h+1)*58+(w+1)][c]
// fp16. Pad pixels stay statically zero. grid (56 h, 32 n), 256 threads.
// ---------------------------------------------------------------------------
__global__ __launch_bounds__(256) void pack_x_kernel(const float* __restrict__ x)
{
    __shared__ __half sm[256][58];
    const int h = blockIdx.x, n = blockIdx.y;
    const int wi = threadIdx.x & 63, cb = threadIdx.x >> 6;   // cb 0..3
    if (wi < 56) {
        const float* src = x + (((size_t)n * 256 + cb) * 56 + h) * 56 + wi;
        #pragma unroll 8
        for (int c8 = 0; c8 < 64; c8++) {
            sm[c8 * 4 + cb][wi] = __float2half(src[(size_t)c8 * 4 * 56 * 56]);
        }
    }
    __syncthreads();
    for (int chunk = threadIdx.x; chunk < 56 * 32; chunk += 256) {
        int w = chunk >> 5, cq = chunk & 31;
        __half tmp[8];
        #pragma unroll
        for (int j = 0; j < 8; j++) tmp[j] = sm[cq * 8 + j][w];
        *(uint4*)(g_xpad + ((size_t)n * PIMG + (h + 1) * PROW + (w + 1)) * CH + cq * 8)
            = *(uint4*)tmp;
    }
}

// dummy: positions conv as launch #4 so ncu's fixed sample window hits it
__global__ void dummy_kernel() {}

// ---------------------------------------------------------------------------
// Kernel 3: conv via mma.sync, flat-58 tiling (3.4% waste vs 12.5%),
// 2-deep cp.async ring, 2 CTAs/SM, fused masked BN stats.
// grid (2 ch-tiles, 26 f-tiles, 32 n) = 1664 CTAs, 256 thr (8 warps: 2m x 4n).
// 24 smem stages = 3 h-taps x 8 blocks of 32 in-ch.
// Output flat f = h*58 + w needs inputs f + r*58 + s.
// ---------------------------------------------------------------------------
__global__ __launch_bounds__(256, 2) void conv_kernel()
{
    extern __shared__ __align__(128) char dsm[];
    __shared__ float sm_s1[128];
    __shared__ float sm_s2[128];

    const int n0  = blockIdx.x * NT;
    const int f0  = blockIdx.y * 128;          // flat output base
    const int nb  = blockIdx.z;
    const int tid = threadIdx.x;
    const int wid = tid >> 5, lane = tid & 31;
    const int g = lane >> 2, t = lane & 3;
    const int warp_m = wid & 1;                // 64 flat pixels each
    const int warp_n = wid >> 1;               // 32 channels each

    float acc[4][4][4];
    #pragma unroll
    for (int a = 0; a < 4; a++)
        #pragma unroll
        for (int b = 0; b < 4; b++)
            #pragma unroll
            for (int c = 0; c < 4; c++) acc[a][b][c] = 0.f;

    if (tid < 128) { sm_s1[tid] = 0.f; sm_s2[tid] = 0.f; }

    const __half* xp = g_xpad + (size_t)nb * PIMG * CH;

    auto load_stage = [&](int st) {
        char* sb = dsm + (st & 1) * STAGE;
        const int r = st >> 3, kb = st & 7;        // kb: 32-ch block
        const int pix0 = f0 + r * PROW;
        // A: 130 consecutive flat pixels x 32 ch (4 x 16B chunks per row)
        #pragma unroll 1
        for (int i = tid; i < AROWS * 4; i += 256) {
            int row = i >> 2, q = i & 3;
            cp16(su32(sb + AOFF + row * RSTRB + q * 16),
                 xp + (size_t)(pix0 + row) * CH + kb * 32 + q * 8);
        }
        // B: 3 taps x 128 out-ch x 32 in-ch
        const __half* wp = g_wpack + (size_t)(r * 3) * 65536 + (size_t)n0 * 256 + kb * 32;
        #pragma unroll 1
        for (int i = tid; i < 1536; i += 256) {
            int tap = i >> 9, rem = i & 511, nn = rem >> 2, q = rem & 3;
            cp16(su32(sb + BOFF + (tap * 128 + nn) * RSTRB + q * 16),
                 wp + (size_t)tap * 65536 + (size_t)nn * 256 + q * 8);
        }
        asm volatile("cp.async.commit_group;" ::: "memory");
    };

    auto compute = [&](int st) {
        const char* sb = dsm + (st & 1) * STAGE;
        const __half* sA = (const __half*)(sb + AOFF);
        const __half* sB = (const __half*)(sb + BOFF);
        #pragma unroll
        for (int s = 0; s < 3; s++) {
            #pragma unroll
            for (int kk = 0; kk < 2; kk++) {
                const int c0 = kk * 16 + 2 * t;
                uint32_t af[4][4];
                #pragma unroll
                for (int mt = 0; mt < 4; mt++) {
                    int row = warp_m * 64 + mt * 16 + g + s;
                    af[mt][0] = *(const uint32_t*)(sA + row * RSTRH + c0);
                    af[mt][1] = *(const uint32_t*)(sA + (row + 8) * RSTRH + c0);
                    af[mt][2] = *(const uint32_t*)(sA + row * RSTRH + c0 + 8);
                    af[mt][3] = *(const uint32_t*)(sA + (row + 8) * RSTRH + c0 + 8);
                }
                uint32_t bf[4][2];
                #pragma unroll
                for (int nt = 0; nt < 4; nt++) {
                    int nn = s * 128 + warp_n * 32 + nt * 8 + g;
                    bf[nt][0] = *(const uint32_t*)(sB + nn * RSTRH + c0);
                    bf[nt][1] = *(const uint32_t*)(sB + nn * RSTRH + c0 + 8);
                }
                #pragma unroll
                for (int mt = 0; mt < 4; mt++) {
                    #pragma unroll
                    for (int nt = 0; nt < 4; nt++) {
                        float* cacc = acc[mt][nt];
                        asm volatile(
                          "mma.sync.aligned.m16n8k16.row.col.f32.f16.f16.f32 "
                          "{%0,%1,%2,%3}, {%4,%5,%6,%7}, {%8,%9}, {%0,%1,%2,%3};\n"
                          : "+f"(cacc[0]), "+f"(cacc[1]), "+f"(cacc[2]), "+f"(cacc[3])
                          : "r"(af[mt][0]), "r"(af[mt][1]), "r"(af[mt][2]), "r"(af[mt][3]),
                            "r"(bf[nt][0]), "r"(bf[nt][1]));
                    }
                }
            }
        }
    };

    load_stage(0);
    load_stage(1);
    #pragma unroll 1
    for (int st = 0; st < 24; st++) {
        if (st < 23)
            asm volatile("cp.async.wait_group 1;" ::: "memory");
        else
            asm volatile("cp.async.wait_group 0;" ::: "memory");
        __syncthreads();                 // stage st visible to all warps
        compute(st);
        if (st + 2 < 24) {
            __syncthreads();             // all warps done reading slot st
            load_stage(st + 2);
        }
    }

    // ---- epilogue: acc -> fp16 NHWC (masked) + fused masked BN stats ----
    float s1[4][2], s2[4][2];
    #pragma unroll
    for (int nt = 0; nt < 4; nt++) { s1[nt][0]=s1[nt][1]=s2[nt][0]=s2[nt][1]=0.f; }

    #pragma unroll
    for (int mt = 0; mt < 4; mt++) {
        const int m0 = warp_m * 64 + mt * 16 + g;
        const int fA = f0 + m0;                 // rows g (regs 0,1)
        const int fB = fA + 8;                  // rows g+8 (regs 2,3)
        const int hA = (fA * 565) >> 15, wA = fA - hA * PROW;
        const int hB = (fB * 565) >> 15, wB = fB - hB * PROW;
        const bool vA = (wA < 56) && (hA < 56);
        const bool vB = (wB < 56) && (hB < 56);
        __half* pA = g_ybuf + ((size_t)((nb * HH + hA) * WW + wA)) * CH;
        __half* pB = g_ybuf + ((size_t)((nb * HH + hB) * WW + wB)) * CH;
        #pragma unroll
        for (int nt = 0; nt < 4; nt++) {
            const int ch0 = n0 + warp_n * 32 + nt * 8 + 2 * t;
            float f0v = acc[mt][nt][0], f1v = acc[mt][nt][1];
            float f2v = acc[mt][nt][2], f3v = acc[mt][nt][3];
            if (vA) {
                *(__half2*)(pA + ch0) = __floats2half2_rn(f0v, f1v);
                s1[nt][0] += f0v;  s2[nt][0] += f0v * f0v;
                s1[nt][1] += f1v;  s2[nt][1] += f1v * f1v;
            }
            if (vB) {
                *(__half2*)(pB + ch0) = __floats2half2_rn(f2v, f3v);
                s1[nt][0] += f2v;  s2[nt][0] += f2v * f2v;
                s1[nt][1] += f3v;  s2[nt][1] += f3v * f3v;
            }
        }
    }
    #pragma unroll
    for (int nt = 0; nt < 4; nt++) {
        #pragma unroll
        for (int p = 0; p < 2; p++) {
            #pragma unroll
            for (int m = 4; m < 32; m <<= 1) {
                s1[nt][p] += __shfl_xor_sync(0xffffffffu, s1[nt][p], m);
                s2[nt][p] += __shfl_xor_sync(0xffffffffu, s2[nt][p], m);
            }
        }
    }
    __syncthreads();
    if (g == 0) {
        #pragma unroll
        for (int nt = 0; nt < 4; nt++) {
            #pragma unroll
            for (int p = 0; p < 2; p++) {
                int chl = warp_n * 32 + nt * 8 + 2 * t + p;
                atomicAdd(&sm_s1[chl], s1[nt][p]);
                atomicAdd(&sm_s2[chl], s2[nt][p]);
            }
        }
    }
    __syncthreads();
    if (tid < 128) {
        atomicAdd(&g_sum[n0 + tid],   sm_s1[tid]);
        atomicAdd(&g_sumsq[n0 + tid], sm_s2[tid]);
    }
}

// ---------------------------------------------------------------------------
// Kernel 4: BN finalize + normalize + ReLU + 2x2 maxpool, -> NCHW fp32
// ---------------------------------------------------------------------------
__global__ __launch_bounds__(256) void pool_kernel(float* __restrict__ out,
                                                   const float* __restrict__ gamma,
                                                   const float* __restrict__ beta)
{
    __shared__ float sm[256 * WO];
    const int ho = blockIdx.x;
    const int n  = blockIdx.y;
    const int c  = threadIdx.x;
    const float inv = 1.f / (float)NPIX;
    const float mean = g_sum[c] * inv;
    const float var  = g_sumsq[c] * inv - mean * mean;
    const float sc = gamma[c] * rsqrtf(var + 1e-5f);
    const float sh = beta[c] - mean * sc;
    const __half* b0 = g_ybuf + ((size_t)(n * HH + 2 * ho) * WW) * CH + c;
    const __half* b1 = b0 + (size_t)WW * CH;
    #pragma unroll 4
    for (int wo = 0; wo < WO; wo++) {
        float a0 = __half2float(b0[(size_t)(2 * wo)     * CH]);
        float a1 = __half2float(b0[(size_t)(2 * wo + 1) * CH]);
        float a2 = __half2float(b1[(size_t)(2 * wo)     * CH]);
        float a3 = __half2float(b1[(size_t)(2 * wo + 1) * CH]);
        float r0 = fmaxf(a0 * sc + sh, 0.f);
        float r1 = fmaxf(a1 * sc + sh, 0.f);
        float r2 = fmaxf(a2 * sc + sh, 0.f);
        float r3 = fmaxf(a3 * sc + sh, 0.f);
        sm[c * WO + wo] = fmaxf(fmaxf(r0, r1), fmaxf(r2, r3));
    }
    __syncthreads();
    for (int i = threadIdx.x; i < 256 * WO; i += 256) {
        int cc = i / WO, wo = i % WO;
        out[(((size_t)n * CH + cc) * HO + ho) * WO + wo] = sm[i];
    }
}

// ---------------------------------------------------------------------------
extern "C" void kernel_launch(void* const* d_in, const int* in_sizes, int n_in,
                              void* d_out, int out_size)
{
    const float* x     = (const float*)d_in[0];
    const float* W     = (const float*)d_in[1];
    const float* gamma = (const float*)d_in[2];
    const float* beta  = (const float*)d_in[3];
    float* out = (float*)d_out;

    pack_w_kernel<<<2304, 256>>>(W);
    pack_x_kernel<<<dim3(HH, BATCH), 256>>>(x);
    dummy_kernel<<<1, 32>>>();          // keep conv in ncu's sample slot (#4)

    cudaFuncSetAttribute(conv_kernel, cudaFuncAttributeMaxDynamicSharedMemorySize, DSMEM);
    conv_kernel<<<dim3(2, MT_PER_IMG, BATCH), 256, DSMEM>>>();

    pool_kernel<<<dim3(HO, BATCH), 256>>>(out, gamma, beta);
}